// round 1
// baseline (speedup 1.0000x reference)
#include <cuda_runtime.h>
#include <cstdint>

// Problem constants (fixed by the dataset)
#define NNODES 50000
#define NFEAT  256
#define NHID   64
#define HOPS   4
#define NEDGES 800000
#define OUTC   (HOPS * NHID)          // 256
#define OUT_ELEMS ((size_t)NNODES * OUTC)

// Scratch: h_all[node][hop*64 + j] = (x @ W[hop] + b[hop])[node][j]
__device__ float g_h[(size_t)NNODES * OUTC];

// ---------------------------------------------------------------------------
// Fused GEMM: for each hop, h = x @ W[hop] + b[hop].
// blockIdx.y = hop (W[hop] is a contiguous row-major [256,64] slab).
// 64x64 output tile per block, 256 threads, 4x4 microtile, BK=32.
// ---------------------------------------------------------------------------
#define BM 64
#define BN 64
#define BK 32

__global__ __launch_bounds__(256) void sign_gemm_kernel(
    const float* __restrict__ x,   // [NNODES, NFEAT]
    const float* __restrict__ W,   // [HOPS, NFEAT, NHID]
    const float* __restrict__ b,   // [HOPS, NHID] (flat == column index of h_all)
    float* __restrict__ h)         // [NNODES, OUTC]
{
    __shared__ float As[BK][BM + 1];   // +1 pad -> conflict-free scattered STS
    __shared__ float Bs[BK][BN];

    const int bm  = blockIdx.x;
    const int hop = blockIdx.y;
    const float* Wh = W + (size_t)hop * NFEAT * NHID;   // [256,64] row-major

    const int tid = threadIdx.x;
    const int tx  = tid & 15;        // 0..15 -> 4 cols each
    const int ty  = tid >> 4;        // 0..15 -> 4 rows each
    const int row0 = bm * BM;

    float acc[4][4] = {};

    for (int k0 = 0; k0 < NFEAT; k0 += BK) {
        // --- load A tile (64 rows x 32 k), transposed into As[k][m] ---
        #pragma unroll
        for (int p = 0; p < 2; p++) {
            int r  = (tid >> 3) + p * 32;       // 0..63
            int c4 = (tid & 7) * 4;             // 0..28
            int gm = row0 + r;
            float4 v = make_float4(0.f, 0.f, 0.f, 0.f);
            if (gm < NNODES)
                v = *(const float4*)(x + (size_t)gm * NFEAT + k0 + c4);
            As[c4 + 0][r] = v.x;
            As[c4 + 1][r] = v.y;
            As[c4 + 2][r] = v.z;
            As[c4 + 3][r] = v.w;
        }
        // --- load B tile (32 k x 64 n) ---
        #pragma unroll
        for (int p = 0; p < 2; p++) {
            int r  = (tid >> 4) + p * 16;       // 0..31
            int c4 = (tid & 15) * 4;            // 0..60
            *(float4*)&Bs[r][c4] =
                *(const float4*)(Wh + (size_t)(k0 + r) * NHID + c4);
        }
        __syncthreads();

        #pragma unroll
        for (int k = 0; k < BK; k++) {
            float a[4];
            #pragma unroll
            for (int i = 0; i < 4; i++) a[i] = As[k][ty * 4 + i];
            float4 bv = *(const float4*)&Bs[k][tx * 4];
            float bb[4] = {bv.x, bv.y, bv.z, bv.w};
            #pragma unroll
            for (int i = 0; i < 4; i++)
                #pragma unroll
                for (int j = 0; j < 4; j++)
                    acc[i][j] += a[i] * bb[j];
        }
        __syncthreads();
    }

    // epilogue: + bias, store into h_all at columns hop*64 + ...
    #pragma unroll
    for (int i = 0; i < 4; i++) {
        int gm = row0 + ty * 4 + i;
        if (gm < NNODES) {
            #pragma unroll
            for (int j = 0; j < 4; j++) {
                int gc = hop * NHID + tx * 4 + j;   // also the flat index into b
                h[(size_t)gm * OUTC + gc] = acc[i][j] + b[gc];
            }
        }
    }
}

// ---------------------------------------------------------------------------
// Zero the output accumulator (harness poisons d_out).
// ---------------------------------------------------------------------------
__global__ void sign_zero_kernel(float* __restrict__ out, size_t n)
{
    size_t i = (size_t)blockIdx.x * blockDim.x + threadIdx.x;
    size_t stride = (size_t)gridDim.x * blockDim.x;
    for (; i < n; i += stride) out[i] = 0.0f;
}

// ---------------------------------------------------------------------------
// Edge scatter: 16 threads per (hop, edge). float4 gather of h[col] (256B
// contiguous per edge), 4 scalar atomicAdds into out[row].
// adj arrays are flat [HOPS*NEDGES], so eg indexes them directly.
// ---------------------------------------------------------------------------
__global__ __launch_bounds__(256) void sign_scatter_kernel(
    const int*   __restrict__ rows,
    const int*   __restrict__ cols,
    const float* __restrict__ vals,
    const float* __restrict__ h,
    float*       __restrict__ out)
{
    const long long TOT = (long long)HOPS * NEDGES * 16;
    long long idx = (long long)blockIdx.x * blockDim.x + threadIdx.x;
    if (idx >= TOT) return;

    const int       lane = (int)(idx & 15);
    const long long eg   = idx >> 4;                 // 0 .. HOPS*NEDGES-1
    const int       hop  = (int)(eg / NEDGES);

    const int   r = rows[eg];
    const int   c = cols[eg];
    const float v = vals[eg];

    const float4 hv = *(const float4*)(h + (size_t)c * OUTC + hop * NHID + lane * 4);
    float* o = out + (size_t)r * OUTC + hop * NHID + lane * 4;

    atomicAdd(o + 0, v * hv.x);
    atomicAdd(o + 1, v * hv.y);
    atomicAdd(o + 2, v * hv.z);
    atomicAdd(o + 3, v * hv.w);
}

// ---------------------------------------------------------------------------
// ELU in place: x if x>0 else exp(x)-1
// ---------------------------------------------------------------------------
__global__ void sign_elu_kernel(float* __restrict__ out, size_t n)
{
    size_t i = (size_t)blockIdx.x * blockDim.x + threadIdx.x;
    size_t stride = (size_t)gridDim.x * blockDim.x;
    for (; i < n; i += stride) {
        float v = out[i];
        out[i] = (v > 0.0f) ? v : expm1f(v);
    }
}

// ---------------------------------------------------------------------------
extern "C" void kernel_launch(void* const* d_in, const int* in_sizes, int n_in,
                              void* d_out, int out_size)
{
    const float* x    = (const float*)d_in[0];   // [50000,256]
    const float* W    = (const float*)d_in[1];   // [4,256,64]
    const float* b    = (const float*)d_in[2];   // [4,64]
    const int*   rows = (const int*)  d_in[3];   // [4,800000]
    const int*   cols = (const int*)  d_in[4];   // [4,800000]
    const float* vals = (const float*)d_in[5];   // [4,800000]
    float* out = (float*)d_out;                  // [50000,256]

    float* h;
    cudaGetSymbolAddress((void**)&h, g_h);

    // 1) zero output accumulator
    sign_zero_kernel<<<2048, 256>>>(out, OUT_ELEMS);

    // 2) fused GEMM (all hops)
    dim3 ggrid((NNODES + BM - 1) / BM, HOPS);
    sign_gemm_kernel<<<ggrid, 256>>>(x, W, b, h);

    // 3) edge scatter (atomics)
    const long long TOT = (long long)HOPS * NEDGES * 16;
    int sblocks = (int)((TOT + 255) / 256);
    sign_scatter_kernel<<<sblocks, 256>>>(rows, cols, vals, h, out);

    // 4) ELU in place
    sign_elu_kernel<<<2048, 256>>>(out, OUT_ELEMS);
}

// round 2
// speedup vs baseline: 2.7205x; 2.7205x over previous
#include <cuda_runtime.h>
#include <cstdint>

// Problem constants (fixed by the dataset)
#define NNODES 50000
#define NFEAT  256
#define NHID   64
#define HOPS   4
#define NEDGES 800000
#define OUTC   (HOPS * NHID)          // 256
#define OUT_ELEMS ((size_t)NNODES * OUTC)

// Scratch: h_all[node][hop*64 + j] = (x @ W[hop] + b[hop])[node][j]
__device__ float g_h[(size_t)NNODES * OUTC];

// ---------------------------------------------------------------------------
// Fused GEMM: for each hop, h = x @ W[hop] + b[hop].
// blockIdx.y = hop. 128x64 tile, 256 threads, 8x4 microtile, BK=16.
// As rows padded to 132 floats (528B) -> LDS.128-aligned, broadcast reads.
// ---------------------------------------------------------------------------
#define BM 128
#define BN 64
#define BK 16
#define APAD 4

__global__ __launch_bounds__(256) void sign_gemm_kernel(
    const float* __restrict__ x,   // [NNODES, NFEAT]
    const float* __restrict__ W,   // [HOPS, NFEAT, NHID]
    const float* __restrict__ b,   // [HOPS, NHID]
    float* __restrict__ h)         // [NNODES, OUTC]
{
    __shared__ float As[BK][BM + APAD];  // transposed A tile
    __shared__ float Bs[BK][BN];

    const int bm  = blockIdx.x;
    const int hop = blockIdx.y;
    const float* Wh = W + (size_t)hop * NFEAT * NHID;

    const int tid = threadIdx.x;
    const int tx  = tid & 15;        // 0..15 -> 4 cols each (n)
    const int ty  = tid >> 4;        // 0..15 -> 8 rows each (m)
    const int row0 = bm * BM;

    float acc[8][4];
    #pragma unroll
    for (int i = 0; i < 8; i++)
        #pragma unroll
        for (int j = 0; j < 4; j++) acc[i][j] = 0.f;

    for (int k0 = 0; k0 < NFEAT; k0 += BK) {
        // --- load A tile (128 rows x 16 k), transposed into As[k][m] ---
        #pragma unroll
        for (int p = 0; p < 2; p++) {
            int r  = (tid >> 2) + p * 64;       // 0..127
            int c4 = (tid & 3) * 4;             // 0,4,8,12
            int gm = row0 + r;
            float4 v = make_float4(0.f, 0.f, 0.f, 0.f);
            if (gm < NNODES)
                v = *(const float4*)(x + (size_t)gm * NFEAT + k0 + c4);
            As[c4 + 0][r] = v.x;
            As[c4 + 1][r] = v.y;
            As[c4 + 2][r] = v.z;
            As[c4 + 3][r] = v.w;
        }
        // --- load B tile (16 k x 64 n) ---
        {
            int r  = tid >> 4;                  // 0..15
            int c4 = (tid & 15) * 4;            // 0..60
            *(float4*)&Bs[r][c4] =
                *(const float4*)(Wh + (size_t)(k0 + r) * NHID + c4);
        }
        __syncthreads();

        #pragma unroll
        for (int k = 0; k < BK; k++) {
            float4 a0 = *(const float4*)&As[k][ty * 8];
            float4 a1 = *(const float4*)&As[k][ty * 8 + 4];
            float4 bv = *(const float4*)&Bs[k][tx * 4];
            float a[8] = {a0.x, a0.y, a0.z, a0.w, a1.x, a1.y, a1.z, a1.w};
            float bb[4] = {bv.x, bv.y, bv.z, bv.w};
            #pragma unroll
            for (int i = 0; i < 8; i++)
                #pragma unroll
                for (int j = 0; j < 4; j++)
                    acc[i][j] += a[i] * bb[j];
        }
        __syncthreads();
    }

    // epilogue: + bias, store into h_all at columns hop*64 + ...
    const int gc0 = hop * NHID + tx * 4;
    float4 bias = *(const float4*)(b + gc0);
    #pragma unroll
    for (int i = 0; i < 8; i++) {
        int gm = row0 + ty * 8 + i;
        if (gm < NNODES) {
            float4 o;
            o.x = acc[i][0] + bias.x;
            o.y = acc[i][1] + bias.y;
            o.z = acc[i][2] + bias.z;
            o.w = acc[i][3] + bias.w;
            *(float4*)(h + (size_t)gm * OUTC + gc0) = o;
        }
    }
}

// ---------------------------------------------------------------------------
// Zero the output accumulator (vectorized; OUT_ELEMS % 4 == 0).
// ---------------------------------------------------------------------------
__global__ void sign_zero_kernel(float4* __restrict__ out, size_t n4)
{
    size_t i = (size_t)blockIdx.x * blockDim.x + threadIdx.x;
    size_t stride = (size_t)gridDim.x * blockDim.x;
    float4 z = make_float4(0.f, 0.f, 0.f, 0.f);
    for (; i < n4; i += stride) out[i] = z;
}

// ---------------------------------------------------------------------------
// Edge scatter: 16 threads per (hop, edge). float4 gather of h[col],
// one red.global.add.v4.f32 per thread (RED.128) into out[row].
// ---------------------------------------------------------------------------
__global__ __launch_bounds__(256) void sign_scatter_kernel(
    const int*   __restrict__ rows,
    const int*   __restrict__ cols,
    const float* __restrict__ vals,
    const float* __restrict__ h,
    float*       __restrict__ out)
{
    const long long TOT = (long long)HOPS * NEDGES * 16;
    long long idx = (long long)blockIdx.x * blockDim.x + threadIdx.x;
    if (idx >= TOT) return;

    const int       lane = (int)(idx & 15);
    const long long eg   = idx >> 4;                 // 0 .. HOPS*NEDGES-1
    const int       hop  = (int)(eg / NEDGES);

    const int   r = rows[eg];
    const int   c = cols[eg];
    const float v = vals[eg];

    const float4 hv = *(const float4*)(h + (size_t)c * OUTC + hop * NHID + lane * 4);
    float* o = out + (size_t)r * OUTC + hop * NHID + lane * 4;

    asm volatile("red.global.add.v4.f32 [%0], {%1, %2, %3, %4};"
                 :: "l"(o), "f"(v * hv.x), "f"(v * hv.y),
                    "f"(v * hv.z), "f"(v * hv.w)
                 : "memory");
}

// ---------------------------------------------------------------------------
// ELU in place (vectorized): x if x>0 else exp(x)-1
// ---------------------------------------------------------------------------
__global__ void sign_elu_kernel(float4* __restrict__ out, size_t n4)
{
    size_t i = (size_t)blockIdx.x * blockDim.x + threadIdx.x;
    size_t stride = (size_t)gridDim.x * blockDim.x;
    for (; i < n4; i += stride) {
        float4 v = out[i];
        v.x = (v.x > 0.0f) ? v.x : expm1f(v.x);
        v.y = (v.y > 0.0f) ? v.y : expm1f(v.y);
        v.z = (v.z > 0.0f) ? v.z : expm1f(v.z);
        v.w = (v.w > 0.0f) ? v.w : expm1f(v.w);
        out[i] = v;
    }
}

// ---------------------------------------------------------------------------
extern "C" void kernel_launch(void* const* d_in, const int* in_sizes, int n_in,
                              void* d_out, int out_size)
{
    const float* x    = (const float*)d_in[0];   // [50000,256]
    const float* W    = (const float*)d_in[1];   // [4,256,64]
    const float* b    = (const float*)d_in[2];   // [4,64]
    const int*   rows = (const int*)  d_in[3];   // [4,800000]
    const int*   cols = (const int*)  d_in[4];   // [4,800000]
    const float* vals = (const float*)d_in[5];   // [4,800000]
    float* out = (float*)d_out;                  // [50000,256]

    float* h;
    cudaGetSymbolAddress((void**)&h, g_h);

    // 1) zero output accumulator
    sign_zero_kernel<<<1184, 256>>>((float4*)out, OUT_ELEMS / 4);

    // 2) fused GEMM (all hops)
    dim3 ggrid((NNODES + BM - 1) / BM, HOPS);
    sign_gemm_kernel<<<ggrid, 256>>>(x, W, b, h);

    // 3) edge scatter (vector atomics)
    const long long TOT = (long long)HOPS * NEDGES * 16;
    int sblocks = (int)((TOT + 255) / 256);
    sign_scatter_kernel<<<sblocks, 256>>>(rows, cols, vals, h, out);

    // 4) ELU in place
    sign_elu_kernel<<<1184, 256>>>((float4*)out, OUT_ELEMS / 4);
}

// round 4
// speedup vs baseline: 3.3510x; 1.2318x over previous
#include <cuda_runtime.h>
#include <cuda_bf16.h>
#include <cstdint>

// Problem constants (fixed by the dataset)
#define NNODES 50000
#define NFEAT  256
#define NHID   64
#define HOPS   4
#define NEDGES 800000
#define OUTC   (HOPS * NHID)          // 256
#define OUT_ELEMS ((size_t)NNODES * OUTC)

// Scratch buffers
__device__ float g_h[(size_t)NNODES * OUTC];               // h_all [node][hop*64+j]
__device__ __nv_bfloat16 g_Wt_hi[HOPS * NHID * NFEAT];      // [hop][n][k] bf16 hi
__device__ __nv_bfloat16 g_Wt_lo[HOPS * NHID * NFEAT];      // [hop][n][k] bf16 lo

__device__ __forceinline__ uint32_t smem_to_u32(const void* smem_ptr) {
    uint32_t addr;
    asm("{ .reg .u64 tmp; cvta.to.shared.u64 tmp, %1; cvt.u32.u64 %0, tmp; }"
        : "=r"(addr) : "l"(smem_ptr));
    return addr;
}

#define LDSM_X4(d, addr) \
    asm volatile("ldmatrix.sync.aligned.m8n8.x4.shared.b16 {%0,%1,%2,%3}, [%4];" \
                 : "=r"((d)[0]), "=r"((d)[1]), "=r"((d)[2]), "=r"((d)[3]) \
                 : "r"(addr))

__device__ __forceinline__ void mma_bf16(float* c, const uint32_t* a, const uint32_t* b)
{
    asm volatile(
        "mma.sync.aligned.m16n8k16.row.col.f32.bf16.bf16.f32 "
        "{%0,%1,%2,%3}, {%4,%5,%6,%7}, {%8,%9}, {%0,%1,%2,%3};"
        : "+f"(c[0]), "+f"(c[1]), "+f"(c[2]), "+f"(c[3])
        : "r"(a[0]), "r"(a[1]), "r"(a[2]), "r"(a[3]), "r"(b[0]), "r"(b[1]));
}

// ---------------------------------------------------------------------------
// W convert+transpose: g_Wt[hop][n][k] = bf16_split(W[hop][k][n])
// ---------------------------------------------------------------------------
__global__ void sign_wconv_kernel(const float* __restrict__ W)
{
    int idx = blockIdx.x * blockDim.x + threadIdx.x;      // 0 .. 4*64*256-1
    if (idx >= HOPS * NHID * NFEAT) return;
    int hop = idx >> 14;
    int n   = (idx >> 8) & 63;
    int k   = idx & 255;
    float v = W[((size_t)hop * NFEAT + k) * NHID + n];
    __nv_bfloat16 hi = __float2bfloat16_rn(v);
    __nv_bfloat16 lo = __float2bfloat16_rn(v - __bfloat162float(hi));
    g_Wt_hi[idx] = hi;
    g_Wt_lo[idx] = lo;
}

// ---------------------------------------------------------------------------
// mma.sync GEMM: CTA = 128 rows x 128 cols (2 hops). bf16 hi/lo 3-term split,
// fp32 register accumulators. SW128-swizzled SMEM + ldmatrix.
// grid = (ceil(N/128), 2)
// ---------------------------------------------------------------------------
#define SM_AHI 0
#define SM_ALO 16384
#define SM_BHI 32768
#define SM_BLO 49152
#define SM_TOTAL 65536
#define KCHUNK 64

__global__ __launch_bounds__(256, 1) void sign_gemm_mma_kernel(
    const float* __restrict__ x,   // [NNODES, NFEAT]
    const float* __restrict__ b,   // [HOPS*NHID]
    float* __restrict__ h)         // [NNODES, OUTC]
{
    extern __shared__ char smem[];
    const uint32_t sbase = smem_to_u32(smem);
    const int tid  = threadIdx.x;
    const int wid  = tid >> 5;
    const int lane = tid & 31;
    const int row0 = blockIdx.x * 128;
    const int cg   = blockIdx.y;              // column group: cols [cg*128, +128)

    const int m0 = (wid >> 1) * 32;           // warp rows  [m0, m0+32)
    const int n0 = (wid & 1) * 64;            // warp cols  [n0, n0+64)

    float acc[2][8][4];
    #pragma unroll
    for (int i = 0; i < 2; i++)
        #pragma unroll
        for (int j = 0; j < 8; j++)
            #pragma unroll
            for (int q = 0; q < 4; q++) acc[i][j][q] = 0.f;

    // per-lane ldmatrix addressing (SW128: xor bits[6:4] with row&7)
    const int a_row = (lane & 7) + ((lane >> 3) & 1) * 8;
    const int a_sel = (lane >> 4) << 4;                 // k-half select (bytes)
    const int b_row = (lane & 7) + (lane >> 4) * 8;
    const int b_sel = ((lane >> 3) & 1) << 4;

    uint32_t aBase[2], aXor[2];
    #pragma unroll
    for (int mt = 0; mt < 2; mt++) {
        int r = m0 + mt * 16 + a_row;
        aBase[mt] = (uint32_t)(r * 128);
        aXor[mt]  = (uint32_t)(((r & 7) << 4) ^ a_sel);
    }
    uint32_t bBase[4], bXor[4];
    #pragma unroll
    for (int nt2 = 0; nt2 < 4; nt2++) {
        int r = n0 + nt2 * 16 + b_row;
        bBase[nt2] = (uint32_t)(r * 128);
        bXor[nt2]  = (uint32_t)(((r & 7) << 4) ^ b_sel);
    }

    for (int chunk = 0; chunk < NFEAT / KCHUNK; chunk++) {
        const int k0 = chunk * KCHUNK;

        // --- A: load 128x64 fp32, split to bf16 hi/lo planes (swizzled) ---
        #pragma unroll
        for (int p = 0; p < 8; p++) {
            int s  = tid + p * 256;            // 0..2047
            int r  = s >> 4;                   // 0..127
            int c4 = (s & 15) * 4;             // 0..60 (floats)
            int gm = row0 + r;
            float4 v = make_float4(0.f, 0.f, 0.f, 0.f);
            if (gm < NNODES)
                v = *(const float4*)(x + (size_t)gm * NFEAT + k0 + c4);
            __nv_bfloat162 h0 = __floats2bfloat162_rn(v.x, v.y);
            __nv_bfloat162 h1 = __floats2bfloat162_rn(v.z, v.w);
            __nv_bfloat162 l0 = __floats2bfloat162_rn(v.x - __bfloat162float(h0.x),
                                                      v.y - __bfloat162float(h0.y));
            __nv_bfloat162 l1 = __floats2bfloat162_rn(v.z - __bfloat162float(h1.x),
                                                      v.w - __bfloat162float(h1.y));
            uint32_t off = (uint32_t)(r * 128) + (uint32_t)((c4 * 2) ^ ((r & 7) << 4));
            uint2 hv, lv;
            hv.x = *(uint32_t*)&h0; hv.y = *(uint32_t*)&h1;
            lv.x = *(uint32_t*)&l0; lv.y = *(uint32_t*)&l1;
            *(uint2*)(smem + SM_AHI + off) = hv;
            *(uint2*)(smem + SM_ALO + off) = lv;
        }

        // --- B: load 128 cols x 64 k bf16 hi/lo from g_Wt (swizzled) ---
        #pragma unroll
        for (int p = 0; p < 8; p++) {
            int s  = tid + p * 256;            // 0..2047
            int r  = s >> 4;                   // 0..127 (local col)
            int kk = s & 15;                   // 8B units along k
            size_t src = (size_t)(cg * 128 + r) * NFEAT + k0 + kk * 4;
            uint2 hv = *(const uint2*)(g_Wt_hi + src);
            uint2 lv = *(const uint2*)(g_Wt_lo + src);
            uint32_t off = (uint32_t)(r * 128) + (uint32_t)((kk * 8) ^ ((r & 7) << 4));
            *(uint2*)(smem + SM_BHI + off) = hv;
            *(uint2*)(smem + SM_BLO + off) = lv;
        }
        __syncthreads();

        // --- MMA over 4 k16 steps ---
        #pragma unroll
        for (int ks = 0; ks < 4; ks++) {
            const uint32_t ks32 = ks * 32;
            uint32_t ah[2][4], al[2][4];
            #pragma unroll
            for (int mt = 0; mt < 2; mt++) {
                uint32_t col = ks32 ^ aXor[mt];
                LDSM_X4(ah[mt], sbase + SM_AHI + aBase[mt] + col);
                LDSM_X4(al[mt], sbase + SM_ALO + aBase[mt] + col);
            }
            #pragma unroll
            for (int nt2 = 0; nt2 < 4; nt2++) {
                uint32_t col = ks32 ^ bXor[nt2];
                uint32_t bh[4], bl[4];
                LDSM_X4(bh, sbase + SM_BHI + bBase[nt2] + col);
                LDSM_X4(bl, sbase + SM_BLO + bBase[nt2] + col);
                #pragma unroll
                for (int half = 0; half < 2; half++) {
                    int nt = nt2 * 2 + half;
                    #pragma unroll
                    for (int mt = 0; mt < 2; mt++) {
                        mma_bf16(acc[mt][nt], ah[mt], &bh[half * 2]);
                        mma_bf16(acc[mt][nt], ah[mt], &bl[half * 2]);
                        mma_bf16(acc[mt][nt], al[mt], &bh[half * 2]);
                    }
                }
            }
        }
        __syncthreads();
    }

    // --- epilogue: bias + store fp32 to g_h ---
    const int er = lane >> 2;          // 0..7
    const int ec = (lane & 3) * 2;     // 0,2,4,6
    #pragma unroll
    for (int mt = 0; mt < 2; mt++) {
        #pragma unroll
        for (int nt = 0; nt < 8; nt++) {
            int gm = row0 + m0 + mt * 16 + er;
            int gc = cg * 128 + n0 + nt * 8 + ec;
            float2 bias = *(const float2*)(b + gc);
            if (gm < NNODES) {
                float2 o; o.x = acc[mt][nt][0] + bias.x; o.y = acc[mt][nt][1] + bias.y;
                *(float2*)(h + (size_t)gm * OUTC + gc) = o;
            }
            if (gm + 8 < NNODES) {
                float2 o; o.x = acc[mt][nt][2] + bias.x; o.y = acc[mt][nt][3] + bias.y;
                *(float2*)(h + (size_t)(gm + 8) * OUTC + gc) = o;
            }
        }
    }
}

// ---------------------------------------------------------------------------
// Zero the output accumulator (vectorized).
// ---------------------------------------------------------------------------
__global__ void sign_zero_kernel(float4* __restrict__ out, size_t n4)
{
    size_t i = (size_t)blockIdx.x * blockDim.x + threadIdx.x;
    size_t stride = (size_t)gridDim.x * blockDim.x;
    float4 z = make_float4(0.f, 0.f, 0.f, 0.f);
    for (; i < n4; i += stride) out[i] = z;
}

// ---------------------------------------------------------------------------
// Edge scatter: 16 threads per (hop, edge); one RED.128 per thread.
// ---------------------------------------------------------------------------
__global__ __launch_bounds__(256) void sign_scatter_kernel(
    const int*   __restrict__ rows,
    const int*   __restrict__ cols,
    const float* __restrict__ vals,
    const float* __restrict__ h,
    float*       __restrict__ out)
{
    const long long TOT = (long long)HOPS * NEDGES * 16;
    long long idx = (long long)blockIdx.x * blockDim.x + threadIdx.x;
    if (idx >= TOT) return;

    const int       lane = (int)(idx & 15);
    const long long eg   = idx >> 4;
    const int       hop  = (int)(eg / NEDGES);

    const int   r = rows[eg];
    const int   c = cols[eg];
    const float v = vals[eg];

    const float4 hv = *(const float4*)(h + (size_t)c * OUTC + hop * NHID + lane * 4);
    float* o = out + (size_t)r * OUTC + hop * NHID + lane * 4;

    asm volatile("red.global.add.v4.f32 [%0], {%1, %2, %3, %4};"
                 :: "l"(o), "f"(v * hv.x), "f"(v * hv.y),
                    "f"(v * hv.z), "f"(v * hv.w)
                 : "memory");
}

// ---------------------------------------------------------------------------
// ELU in place (vectorized)
// ---------------------------------------------------------------------------
__global__ void sign_elu_kernel(float4* __restrict__ out, size_t n4)
{
    size_t i = (size_t)blockIdx.x * blockDim.x + threadIdx.x;
    size_t stride = (size_t)gridDim.x * blockDim.x;
    for (; i < n4; i += stride) {
        float4 v = out[i];
        v.x = (v.x > 0.0f) ? v.x : expm1f(v.x);
        v.y = (v.y > 0.0f) ? v.y : expm1f(v.y);
        v.z = (v.z > 0.0f) ? v.z : expm1f(v.z);
        v.w = (v.w > 0.0f) ? v.w : expm1f(v.w);
        out[i] = v;
    }
}

// ---------------------------------------------------------------------------
extern "C" void kernel_launch(void* const* d_in, const int* in_sizes, int n_in,
                              void* d_out, int out_size)
{
    const float* x    = (const float*)d_in[0];
    const float* W    = (const float*)d_in[1];
    const float* b    = (const float*)d_in[2];
    const int*   rows = (const int*)  d_in[3];
    const int*   cols = (const int*)  d_in[4];
    const float* vals = (const float*)d_in[5];
    float* out = (float*)d_out;

    float* h;
    cudaGetSymbolAddress((void**)&h, g_h);

    cudaFuncSetAttribute(sign_gemm_mma_kernel,
                         cudaFuncAttributeMaxDynamicSharedMemorySize, SM_TOTAL);

    // 0) W convert + transpose (tiny)
    sign_wconv_kernel<<<(HOPS * NHID * NFEAT + 255) / 256, 256>>>(W);

    // 1) zero output accumulator
    sign_zero_kernel<<<1184, 256>>>((float4*)out, OUT_ELEMS / 4);

    // 2) tensor-core GEMM via mma.sync (2 hops per CTA, x read twice -> L2)
    dim3 ggrid((NNODES + 127) / 128, 2);
    sign_gemm_mma_kernel<<<ggrid, 256, SM_TOTAL>>>(x, b, h);

    // 3) edge scatter (vector atomics)
    const long long TOT = (long long)HOPS * NEDGES * 16;
    int sblocks = (int)((TOT + 255) / 256);
    sign_scatter_kernel<<<sblocks, 256>>>(rows, cols, vals, h, out);

    // 4) ELU in place
    sign_elu_kernel<<<1184, 256>>>((float4*)out, OUT_ELEMS / 4);
}

// round 6
// speedup vs baseline: 4.2835x; 1.2783x over previous
#include <cuda_runtime.h>
#include <cuda_bf16.h>
#include <cuda_fp16.h>
#include <cstdint>

// Problem constants (fixed by the dataset)
#define NNODES 50000
#define NFEAT  256
#define NHID   64
#define HOPS   4
#define NEDGES 800000
#define OUTC   (HOPS * NHID)          // 256
#define NSEG   (NNODES * HOPS)        // 200000 segments
#define TOTE   (HOPS * NEDGES)        // 3.2M edges

// Scratch buffers
__device__ __half g_h[(size_t)NNODES * OUTC];               // h (fp16) [node][hop*64+j]
__device__ __nv_bfloat16 g_Wt_hi[HOPS * NHID * NFEAT];      // [hop][n][k] bf16 hi
__device__ __nv_bfloat16 g_Wt_lo[HOPS * NHID * NFEAT];      // [hop][n][k] bf16 lo
__device__ int   g_counts[NSEG];
__device__ int   g_offsets[NSEG];
__device__ int   g_head[NSEG];
__device__ uint2 g_sorted[TOTE];                            // packed (col, val_bits)

#define SCAN_CHUNK 2048
#define NSCANBLK ((NSEG + SCAN_CHUNK - 1) / SCAN_CHUNK)     // 98
__device__ int g_blksum[NSCANBLK];
__device__ int g_blkoff[NSCANBLK];

__device__ __forceinline__ uint32_t smem_to_u32(const void* smem_ptr) {
    uint32_t addr;
    asm("{ .reg .u64 tmp; cvta.to.shared.u64 tmp, %1; cvt.u32.u64 %0, tmp; }"
        : "=r"(addr) : "l"(smem_ptr));
    return addr;
}

#define LDSM_X4(d, addr) \
    asm volatile("ldmatrix.sync.aligned.m8n8.x4.shared.b16 {%0,%1,%2,%3}, [%4];" \
                 : "=r"((d)[0]), "=r"((d)[1]), "=r"((d)[2]), "=r"((d)[3]) \
                 : "r"(addr))

__device__ __forceinline__ void mma_bf16(float* c, const uint32_t* a, const uint32_t* b)
{
    asm volatile(
        "mma.sync.aligned.m16n8k16.row.col.f32.bf16.bf16.f32 "
        "{%0,%1,%2,%3}, {%4,%5,%6,%7}, {%8,%9}, {%0,%1,%2,%3};"
        : "+f"(c[0]), "+f"(c[1]), "+f"(c[2]), "+f"(c[3])
        : "r"(a[0]), "r"(a[1]), "r"(a[2]), "r"(a[3]), "r"(b[0]), "r"(b[1]));
}

// ---------------------------------------------------------------------------
// W convert+transpose: g_Wt[hop][n][k] = bf16_split(W[hop][k][n])
// ---------------------------------------------------------------------------
__global__ void sign_wconv_kernel(const float* __restrict__ W)
{
    int idx = blockIdx.x * blockDim.x + threadIdx.x;
    if (idx >= HOPS * NHID * NFEAT) return;
    int hop = idx >> 14;
    int n   = (idx >> 8) & 63;
    int k   = idx & 255;
    float v = W[((size_t)hop * NFEAT + k) * NHID + n];
    __nv_bfloat16 hi = __float2bfloat16_rn(v);
    __nv_bfloat16 lo = __float2bfloat16_rn(v - __bfloat162float(hi));
    g_Wt_hi[idx] = hi;
    g_Wt_lo[idx] = lo;
}

// ---------------------------------------------------------------------------
// mma.sync GEMM: CTA = 128 rows x 128 cols (2 hops). bf16 hi/lo 3-term split,
// fp32 register accumulators, fp16 output. grid = (ceil(N/128), 2)
// ---------------------------------------------------------------------------
#define SM_AHI 0
#define SM_ALO 16384
#define SM_BHI 32768
#define SM_BLO 49152
#define SM_TOTAL 65536
#define KCHUNK 64

__global__ __launch_bounds__(256, 1) void sign_gemm_mma_kernel(
    const float* __restrict__ x,   // [NNODES, NFEAT]
    const float* __restrict__ b,   // [HOPS*NHID]
    __half* __restrict__ h)        // [NNODES, OUTC] fp16
{
    extern __shared__ char smem[];
    const uint32_t sbase = smem_to_u32(smem);
    const int tid  = threadIdx.x;
    const int wid  = tid >> 5;
    const int lane = tid & 31;
    const int row0 = blockIdx.x * 128;
    const int cg   = blockIdx.y;

    const int m0 = (wid >> 1) * 32;
    const int n0 = (wid & 1) * 64;

    float acc[2][8][4];
    #pragma unroll
    for (int i = 0; i < 2; i++)
        #pragma unroll
        for (int j = 0; j < 8; j++)
            #pragma unroll
            for (int q = 0; q < 4; q++) acc[i][j][q] = 0.f;

    const int a_row = (lane & 7) + ((lane >> 3) & 1) * 8;
    const int a_sel = (lane >> 4) << 4;
    const int b_row = (lane & 7) + (lane >> 4) * 8;
    const int b_sel = ((lane >> 3) & 1) << 4;

    uint32_t aBase[2], aXor[2];
    #pragma unroll
    for (int mt = 0; mt < 2; mt++) {
        int r = m0 + mt * 16 + a_row;
        aBase[mt] = (uint32_t)(r * 128);
        aXor[mt]  = (uint32_t)(((r & 7) << 4) ^ a_sel);
    }
    uint32_t bBase[4], bXor[4];
    #pragma unroll
    for (int nt2 = 0; nt2 < 4; nt2++) {
        int r = n0 + nt2 * 16 + b_row;
        bBase[nt2] = (uint32_t)(r * 128);
        bXor[nt2]  = (uint32_t)(((r & 7) << 4) ^ b_sel);
    }

    for (int chunk = 0; chunk < NFEAT / KCHUNK; chunk++) {
        const int k0 = chunk * KCHUNK;

        #pragma unroll
        for (int p = 0; p < 8; p++) {
            int s  = tid + p * 256;
            int r  = s >> 4;
            int c4 = (s & 15) * 4;
            int gm = row0 + r;
            float4 v = make_float4(0.f, 0.f, 0.f, 0.f);
            if (gm < NNODES)
                v = *(const float4*)(x + (size_t)gm * NFEAT + k0 + c4);
            __nv_bfloat162 h0 = __floats2bfloat162_rn(v.x, v.y);
            __nv_bfloat162 h1 = __floats2bfloat162_rn(v.z, v.w);
            __nv_bfloat162 l0 = __floats2bfloat162_rn(v.x - __bfloat162float(h0.x),
                                                      v.y - __bfloat162float(h0.y));
            __nv_bfloat162 l1 = __floats2bfloat162_rn(v.z - __bfloat162float(h1.x),
                                                      v.w - __bfloat162float(h1.y));
            uint32_t off = (uint32_t)(r * 128) + (uint32_t)((c4 * 2) ^ ((r & 7) << 4));
            uint2 hv, lv;
            hv.x = *(uint32_t*)&h0; hv.y = *(uint32_t*)&h1;
            lv.x = *(uint32_t*)&l0; lv.y = *(uint32_t*)&l1;
            *(uint2*)(smem + SM_AHI + off) = hv;
            *(uint2*)(smem + SM_ALO + off) = lv;
        }

        #pragma unroll
        for (int p = 0; p < 8; p++) {
            int s  = tid + p * 256;
            int r  = s >> 4;
            int kk = s & 15;
            size_t src = (size_t)(cg * 128 + r) * NFEAT + k0 + kk * 4;
            uint2 hv = *(const uint2*)(g_Wt_hi + src);
            uint2 lv = *(const uint2*)(g_Wt_lo + src);
            uint32_t off = (uint32_t)(r * 128) + (uint32_t)((kk * 8) ^ ((r & 7) << 4));
            *(uint2*)(smem + SM_BHI + off) = hv;
            *(uint2*)(smem + SM_BLO + off) = lv;
        }
        __syncthreads();

        #pragma unroll
        for (int ks = 0; ks < 4; ks++) {
            const uint32_t ks32 = ks * 32;
            uint32_t ah[2][4], al[2][4];
            #pragma unroll
            for (int mt = 0; mt < 2; mt++) {
                uint32_t col = ks32 ^ aXor[mt];
                LDSM_X4(ah[mt], sbase + SM_AHI + aBase[mt] + col);
                LDSM_X4(al[mt], sbase + SM_ALO + aBase[mt] + col);
            }
            #pragma unroll
            for (int nt2 = 0; nt2 < 4; nt2++) {
                uint32_t col = ks32 ^ bXor[nt2];
                uint32_t bh[4], bl[4];
                LDSM_X4(bh, sbase + SM_BHI + bBase[nt2] + col);
                LDSM_X4(bl, sbase + SM_BLO + bBase[nt2] + col);
                #pragma unroll
                for (int half = 0; half < 2; half++) {
                    int nt = nt2 * 2 + half;
                    #pragma unroll
                    for (int mt = 0; mt < 2; mt++) {
                        mma_bf16(acc[mt][nt], ah[mt], &bh[half * 2]);
                        mma_bf16(acc[mt][nt], ah[mt], &bl[half * 2]);
                        mma_bf16(acc[mt][nt], al[mt], &bh[half * 2]);
                    }
                }
            }
        }
        __syncthreads();
    }

    // epilogue: bias + fp16 store
    const int er = lane >> 2;
    const int ec = (lane & 3) * 2;
    #pragma unroll
    for (int mt = 0; mt < 2; mt++) {
        #pragma unroll
        for (int nt = 0; nt < 8; nt++) {
            int gm = row0 + m0 + mt * 16 + er;
            int gc = cg * 128 + n0 + nt * 8 + ec;
            float2 bias = *(const float2*)(b + gc);
            if (gm < NNODES) {
                __half2 o = __floats2half2_rn(acc[mt][nt][0] + bias.x,
                                              acc[mt][nt][1] + bias.y);
                *(__half2*)(h + (size_t)gm * OUTC + gc) = o;
            }
            if (gm + 8 < NNODES) {
                __half2 o = __floats2half2_rn(acc[mt][nt][2] + bias.x,
                                              acc[mt][nt][3] + bias.y);
                *(__half2*)(h + (size_t)(gm + 8) * OUTC + gc) = o;
            }
        }
    }
}

// ---------------------------------------------------------------------------
// Bucketing phase 0: zero segment counters.
// ---------------------------------------------------------------------------
__global__ void sign_zero_counts_kernel(void)
{
    int i = blockIdx.x * blockDim.x + threadIdx.x;
    if (i < NSEG) g_counts[i] = 0;
}

// Phase 1: histogram  seg = hop*NNODES + row
__global__ void sign_hist_kernel(const int* __restrict__ rows)
{
    int e   = blockIdx.x * blockDim.x + threadIdx.x;
    int hop = blockIdx.y;
    if (e >= NEDGES) return;
    int r = rows[hop * NEDGES + e];
    atomicAdd(&g_counts[hop * NNODES + r], 1);
}

// Phase 2a: per-block (2048-chunk) reduction of counts
__global__ __launch_bounds__(256) void sign_scan_reduce_kernel(void)
{
    __shared__ int ssum[256];
    int base = blockIdx.x * SCAN_CHUNK;
    int t = threadIdx.x;
    int s = 0;
    #pragma unroll
    for (int j = 0; j < 8; j++) {
        int idx = base + t * 8 + j;
        if (idx < NSEG) s += g_counts[idx];
    }
    ssum[t] = s;
    __syncthreads();
    for (int off = 128; off; off >>= 1) {
        if (t < off) ssum[t] += ssum[t + off];
        __syncthreads();
    }
    if (t == 0) g_blksum[blockIdx.x] = ssum[0];
}

// Phase 2b: exclusive scan of block sums (tiny, serial)
__global__ void sign_scan_blks_kernel(void)
{
    if (threadIdx.x == 0 && blockIdx.x == 0) {
        int acc = 0;
        for (int i = 0; i < NSCANBLK; i++) {
            int v = g_blksum[i];
            g_blkoff[i] = acc;
            acc += v;
        }
    }
}

// Phase 2c: final exclusive scan within each chunk; writes offsets + head
__global__ __launch_bounds__(256) void sign_scan_final_kernel(void)
{
    __shared__ int wsum[8];
    int base = blockIdx.x * SCAN_CHUNK;
    int t = threadIdx.x;
    int lane = t & 31, w = t >> 5;

    int v[8];
    int s = 0;
    #pragma unroll
    for (int j = 0; j < 8; j++) {
        int idx = base + t * 8 + j;
        v[j] = (idx < NSEG) ? g_counts[idx] : 0;
        s += v[j];
    }
    // warp inclusive scan of thread totals
    int incl = s;
    #pragma unroll
    for (int off = 1; off < 32; off <<= 1) {
        int n = __shfl_up_sync(0xFFFFFFFFu, incl, off);
        if (lane >= off) incl += n;
    }
    if (lane == 31) wsum[w] = incl;
    __syncthreads();
    if (w == 0 && lane < 8) {
        int ws = wsum[lane];
        int wincl = ws;
        #pragma unroll
        for (int off = 1; off < 8; off <<= 1) {
            int n = __shfl_up_sync(0xFFu, wincl, off);
            if (lane >= off) wincl += n;
        }
        wsum[lane] = wincl - ws;   // exclusive warp offset
    }
    __syncthreads();

    int run = (incl - s) + wsum[w] + g_blkoff[blockIdx.x];
    #pragma unroll
    for (int j = 0; j < 8; j++) {
        int idx = base + t * 8 + j;
        if (idx < NSEG) {
            g_offsets[idx] = run;
            g_head[idx]    = run;
        }
        run += v[j];
    }
}

// Phase 3: fill sorted edge list (packed col + val bits)
__global__ void sign_fill_kernel(const int* __restrict__ rows,
                                 const int* __restrict__ cols,
                                 const float* __restrict__ vals)
{
    int e   = blockIdx.x * blockDim.x + threadIdx.x;
    int hop = blockIdx.y;
    if (e >= NEDGES) return;
    int idx = hop * NEDGES + e;
    int r = rows[idx];
    int pos = atomicAdd(&g_head[hop * NNODES + r], 1);
    g_sorted[pos] = make_uint2((uint32_t)cols[idx], __float_as_uint(vals[idx]));
}

// Phase 4: segment accumulate + ELU, one warp per (node,hop) segment.
// Lane owns 2 output floats; per edge: 1 broadcast LDG.64 + 1 coalesced
// 128B fp16 gather wavefront. No atomics, single coalesced store.
__global__ __launch_bounds__(256) void sign_accum_kernel(float* __restrict__ out)
{
    const int wid  = threadIdx.x >> 5;
    const int lane = threadIdx.x & 31;
    const int seg  = blockIdx.x * 8 + wid;
    if (seg >= NSEG) return;

    const int hop = seg / NNODES;
    const int row = seg - hop * NNODES;
    const int start = g_offsets[seg];
    const int end   = (seg == NSEG - 1) ? TOTE : g_offsets[seg + 1];
    const int coloff = hop * NHID + lane * 2;

    float ax = 0.f, ay = 0.f;
    int i = start;
    for (; i + 1 < end; i += 2) {
        uint2 cv0 = g_sorted[i];
        uint2 cv1 = g_sorted[i + 1];
        __half2 h0 = *(const __half2*)(g_h + (size_t)cv0.x * OUTC + coloff);
        __half2 h1 = *(const __half2*)(g_h + (size_t)cv1.x * OUTC + coloff);
        float v0 = __uint_as_float(cv0.y);
        float v1 = __uint_as_float(cv1.y);
        float2 f0 = __half22float2(h0);
        float2 f1 = __half22float2(h1);
        ax += v0 * f0.x; ay += v0 * f0.y;
        ax += v1 * f1.x; ay += v1 * f1.y;
    }
    if (i < end) {
        uint2 cv = g_sorted[i];
        __half2 hh = *(const __half2*)(g_h + (size_t)cv.x * OUTC + coloff);
        float v = __uint_as_float(cv.y);
        float2 f = __half22float2(hh);
        ax += v * f.x; ay += v * f.y;
    }

    // ELU fused
    ax = (ax > 0.f) ? ax : expm1f(ax);
    ay = (ay > 0.f) ? ay : expm1f(ay);
    float2 o; o.x = ax; o.y = ay;
    *(float2*)(out + (size_t)row * OUTC + coloff) = o;
}

// ---------------------------------------------------------------------------
extern "C" void kernel_launch(void* const* d_in, const int* in_sizes, int n_in,
                              void* d_out, int out_size)
{
    const float* x    = (const float*)d_in[0];
    const float* W    = (const float*)d_in[1];
    const float* b    = (const float*)d_in[2];
    const int*   rows = (const int*)  d_in[3];
    const int*   cols = (const int*)  d_in[4];
    const float* vals = (const float*)d_in[5];
    float* out = (float*)d_out;

    __half* h;
    cudaGetSymbolAddress((void**)&h, g_h);

    cudaFuncSetAttribute(sign_gemm_mma_kernel,
                         cudaFuncAttributeMaxDynamicSharedMemorySize, SM_TOTAL);

    // GEMM path
    sign_wconv_kernel<<<(HOPS * NHID * NFEAT + 255) / 256, 256>>>(W);
    dim3 ggrid((NNODES + 127) / 128, 2);
    sign_gemm_mma_kernel<<<ggrid, 256, SM_TOTAL>>>(x, b, h);

    // Bucketing path (independent of GEMM; stream-serial is fine)
    sign_zero_counts_kernel<<<(NSEG + 255) / 256, 256>>>();
    dim3 egrid((NEDGES + 255) / 256, HOPS);
    sign_hist_kernel<<<egrid, 256>>>(rows);
    sign_scan_reduce_kernel<<<NSCANBLK, 256>>>();
    sign_scan_blks_kernel<<<1, 32>>>();
    sign_scan_final_kernel<<<NSCANBLK, 256>>>();
    sign_fill_kernel<<<egrid, 256>>>(rows, cols, vals);

    // Segment accumulate + ELU (writes every output element)
    sign_accum_kernel<<<(NSEG + 7) / 8, 256>>>(out);
}